// round 8
// baseline (speedup 1.0000x reference)
#include <cuda_runtime.h>

// QuantumAutoencoder strip-pool + cos. In: [32768,3,32,32] f32 -> Out: [32768,64] f32.
// Persistent single-wave grid (148 SMs x 8 blocks x 256 thr = full occupancy),
// grid-stride over images (2 per block per iter) to remove all wave transitions.
// float4-slot t (0..255) is the same spatial position across the 3 channels
// (offsets t, t+256, t+512); patch p = slots 4p..4p+3 -> shfl_xor reduce.

#define PI_F 3.14159265358979323846f

__global__ void __launch_bounds__(256) qae_kernel(const float4* __restrict__ in,
                                                  float* __restrict__ out,
                                                  int n_img) {
    int t = threadIdx.x;                       // 0..255
    int stride = gridDim.x * 2;                // images advanced per iteration

    for (int img0 = blockIdx.x * 2; img0 < n_img; img0 += stride) {
        float s[2];
        #pragma unroll
        for (int i = 0; i < 2; ++i) {
            const float4* p = in + (size_t)(img0 + i) * 768;  // 3*1024/4
            float4 a = __ldcs(p + t);
            float4 b = __ldcs(p + t + 256);
            float4 c = __ldcs(p + t + 512);
            s[i] = ((a.x + a.y) + (a.z + a.w))
                 + ((b.x + b.y) + (b.z + b.w))
                 + ((c.x + c.y) + (c.z + c.w));
        }

        #pragma unroll
        for (int i = 0; i < 2; ++i) {
            float v = s[i];
            v += __shfl_xor_sync(0xffffffffu, v, 1);
            v += __shfl_xor_sync(0xffffffffu, v, 2);
            if ((t & 3) == 0) {
                float mean = v * (1.0f / 48.0f);
                float ang = mean * (PI_F / 255.0f) - (PI_F * 0.5f);
                __stcs(&out[(size_t)(img0 + i) * 64 + (t >> 2)], cosf(ang));
            }
        }
    }
}

extern "C" void kernel_launch(void* const* d_in, const int* in_sizes, int n_in,
                              void* d_out, int out_size) {
    const float4* in = (const float4*)d_in[0];
    float* out = (float*)d_out;
    int n_img = in_sizes[0] / (3 * 32 * 32);     // 32768
    int blocks = 148 * 8;                        // one full wave on 148 SMs
    qae_kernel<<<blocks, 256>>>(in, out, n_img);
}

// round 9
// speedup vs baseline: 1.0377x; 1.0377x over previous
#include <cuda_runtime.h>

// QuantumAutoencoder strip-pool + cos. In: [32768,3,32,32] f32 -> Out: [32768,64] f32.
// Terminal config (R6): flat grid, 2 imgs/block, 256 thr, regs 32, streaming hints.
// float4-slot t (0..255) is the same spatial position across the 3 channels
// (offsets t, t+256, t+512 in float4 units); warp loads are 512B contiguous.
// Patch p = slots 4p..4p+3 -> 2-step shfl_xor reduce; lane (t&3)==0 stores
// (8 consecutive floats per warp = one full 32B sector).
// Measured at the B300 LTS path-independent throughput cap (~6.74 TB/s).

#define PI_F 3.14159265358979323846f
#define IMGS_PER_BLOCK 2

__global__ void __launch_bounds__(256) qae_kernel(const float4* __restrict__ in,
                                                  float* __restrict__ out) {
    int t = threadIdx.x;                       // 0..255
    int img0 = blockIdx.x * IMGS_PER_BLOCK;

    float s[IMGS_PER_BLOCK];
    #pragma unroll
    for (int i = 0; i < IMGS_PER_BLOCK; ++i) {
        const float4* p = in + (size_t)(img0 + i) * 768;  // 3*1024/4
        float4 a = __ldcs(p + t);
        float4 b = __ldcs(p + t + 256);
        float4 c = __ldcs(p + t + 512);
        s[i] = ((a.x + a.y) + (a.z + a.w))
             + ((b.x + b.y) + (b.z + b.w))
             + ((c.x + c.y) + (c.z + c.w));
    }

    #pragma unroll
    for (int i = 0; i < IMGS_PER_BLOCK; ++i) {
        float v = s[i];
        v += __shfl_xor_sync(0xffffffffu, v, 1);
        v += __shfl_xor_sync(0xffffffffu, v, 2);
        if ((t & 3) == 0) {
            float mean = v * (1.0f / 48.0f);
            float ang = mean * (PI_F / 255.0f) - (PI_F * 0.5f);
            __stcs(&out[(size_t)(img0 + i) * 64 + (t >> 2)], cosf(ang));
        }
    }
}

extern "C" void kernel_launch(void* const* d_in, const int* in_sizes, int n_in,
                              void* d_out, int out_size) {
    const float4* in = (const float4*)d_in[0];
    float* out = (float*)d_out;
    int n_img = in_sizes[0] / (3 * 32 * 32);     // 32768
    int blocks = n_img / IMGS_PER_BLOCK;         // 16384
    qae_kernel<<<blocks, 256>>>(in, out);
}